// round 8
// baseline (speedup 1.0000x reference)
#include <cuda_runtime.h>

typedef unsigned long long ull;

#define DIM 16

// Prep-kernel outputs (batch-uniform), for the 8 weight RYs of layers 1,2:
//  g_tpk[r] = packed (t, t), t = tan(w[4+r]/2)
//  g_sc2    = packed (S, S), S = (prod_r cos(w[4+r]/2))^2  (deferred scale)
//  g_h0[q]  = 0.5f * w[q]   layer-0 weights, fused into input angles
__device__ __align__(16) ull   g_tpk[8];
__device__ ull                 g_sc2;
__device__ __align__(16) float g_h0[4];

// ---------- packed f32x2 helpers ----------
__device__ __forceinline__ ull pk2(float lo, float hi) {
    ull r; asm("mov.b64 %0, {%1, %2};" : "=l"(r) : "f"(lo), "f"(hi)); return r;
}
__device__ __forceinline__ void upk2(ull v, float& lo, float& hi) {
    asm("mov.b64 {%0, %1}, %2;" : "=f"(lo), "=f"(hi) : "l"(v));
}
__device__ __forceinline__ ull f2mul(ull a, ull b) {
    ull r; asm("mul.rn.f32x2 %0, %1, %2;" : "=l"(r) : "l"(a), "l"(b)); return r;
}
__device__ __forceinline__ ull f2add(ull a, ull b) {
    ull r; asm("add.rn.f32x2 %0, %1, %2;" : "=l"(r) : "l"(a), "l"(b)); return r;
}
__device__ __forceinline__ ull f2fma(ull a, ull b, ull c) {
    ull r; asm("fma.rn.f32x2 %0, %1, %2, %3;" : "=l"(r) : "l"(a), "l"(b), "l"(c)); return r;
}
// a - b  ==  fma((-1,-1), b, a): one fma-pipe op.
#define NEG1_PK 0xBF800000BF800000ULL
__device__ __forceinline__ ull f2sub(ull a, ull b) { return f2fma(NEG1_PK, b, a); }
// packed negate: flip both fp32 sign bits (ALU pipe - near idle here).
__device__ __forceinline__ ull f2neg(ull a) { return a ^ 0x8000000080000000ULL; }

// ---------- prep: weight trig, once per launch (single warp, trivial) ----------
__global__ void prep_kernel(const float* __restrict__ w) {
    int k = threadIdx.x;
    if (k < 4) {
        g_h0[k] = 0.5f * w[k];
    }
    if (k >= 4 && k < 12) {
        float s, c;
        sincosf(0.5f * w[k], &s, &c);
        float t = s / c;
        g_tpk[k - 4] = pk2(t, t);
    }
    if (k == 0) {
        float prod = 1.0f;
        for (int r = 0; r < 8; r++) prod *= cosf(0.5f * w[4 + r]);
        float sc2 = prod * prod;
        g_sc2 = pk2(sc2, sc2);
    }
}

// Ring-CNOT permutation: new_state[i] = state[PERM[i]] (free register rename).
__device__ __forceinline__ void apply_perm(ull st[DIM]) {
    const int PERM[DIM] = {0, 13, 3, 14, 6, 11, 5, 8, 12, 1, 15, 2, 10, 7, 9, 4};
    ull tmp[DIM];
#pragma unroll
    for (int i = 0; i < DIM; i++) tmp[i] = st[PERM[i]];
#pragma unroll
    for (int i = 0; i < DIM; i++) st[i] = tmp[i];
}

// Tangent-shear RY on bit (scale c deferred): u' = u - t*v ; v' = t*u + v
// T2 loaded at use site (uniform L1 broadcast) to keep live ranges short.
__device__ __forceinline__ void apply_ry_shear(ull st[DIM], int bit, const ull* tp) {
    const ull T2  = __ldg(tp);
    const ull NT2 = f2neg(T2);
    const int stride = 1 << bit;
#pragma unroll
    for (int i = 0; i < DIM; i++) {
        if (i & stride) continue;
        ull u = st[i];
        ull v = st[i + stride];
        st[i]          = f2fma(NT2, v, u);
        st[i + stride] = f2fma(T2, u, v);
    }
}

__global__ void __launch_bounds__(128, 12)
qlayer_kernel(const float4* __restrict__ x, float4* __restrict__ out, int B2) {
    int t = blockIdx.x * blockDim.x + threadIdx.x;
    if (t >= B2) return;

    float4 xa = x[2 * t];
    float4 xb = x[2 * t + 1];
    float4 h  = *(const float4*)g_h0;

    // Fused layer-0 angles: theta_q/2 = 0.5*x_q + 0.5*w_0q, then fast sincos.
    float ca[4], sa[4], cb[4], sb[4];
    __sincosf(fmaf(0.5f, xa.x, h.x), &sa[0], &ca[0]);
    __sincosf(fmaf(0.5f, xa.y, h.y), &sa[1], &ca[1]);
    __sincosf(fmaf(0.5f, xa.z, h.z), &sa[2], &ca[2]);
    __sincosf(fmaf(0.5f, xa.w, h.w), &sa[3], &ca[3]);
    __sincosf(fmaf(0.5f, xb.x, h.x), &sb[0], &cb[0]);
    __sincosf(fmaf(0.5f, xb.y, h.y), &sb[1], &cb[1]);
    __sincosf(fmaf(0.5f, xb.z, h.z), &sb[2], &cb[2]);
    __sincosf(fmaf(0.5f, xb.w, h.w), &sb[3], &cb[3]);

    ull C[4], S[4];
#pragma unroll
    for (int q = 0; q < 4; q++) {
        C[q] = pk2(ca[q], cb[q]);
        S[q] = pk2(sa[q], sb[q]);
    }

    // Tensor-product initial state (bit layout: qubit q <-> bit 3-q).
    ull A[4]  = {f2mul(C[0], C[1]), f2mul(C[0], S[1]), f2mul(S[0], C[1]), f2mul(S[0], S[1])};
    ull Bv[4] = {f2mul(C[2], C[3]), f2mul(C[2], S[3]), f2mul(S[2], C[3]), f2mul(S[2], S[3])};

    ull st[DIM];
#pragma unroll
    for (int i = 0; i < DIM; i++) st[i] = f2mul(A[i >> 2], Bv[i & 3]);

    // Layer 0's RYs are fused above -> just its ring permutation.
    apply_perm(st);

    // Layers 1,2: 4 tangent-shear RYs + permutation each (cos scales deferred).
#pragma unroll
    for (int L = 0; L < 2; L++) {
#pragma unroll
        for (int q = 0; q < 4; q++) {
            apply_ry_shear(st, 3 - q, &g_tpk[L * 4 + q]);
        }
        apply_perm(st);
    }

    // Probabilities + shared sum/difference tree for the 4 Z expectations.
    ull p[DIM];
#pragma unroll
    for (int i = 0; i < DIM; i++) p[i] = f2mul(st[i], st[i]);

    ull s2v[8], d2v[8];
#pragma unroll
    for (int k = 0; k < 8; k++) {
        s2v[k] = f2add(p[2 * k], p[2 * k + 1]);
        d2v[k] = f2sub(p[2 * k], p[2 * k + 1]);
    }
    ull s4v[4], d4v[4];
#pragma unroll
    for (int k = 0; k < 4; k++) {
        s4v[k] = f2add(s2v[2 * k], s2v[2 * k + 1]);
        d4v[k] = f2sub(s2v[2 * k], s2v[2 * k + 1]);
    }
    ull s8v[2], d8v[2];
#pragma unroll
    for (int k = 0; k < 2; k++) {
        s8v[k] = f2add(s4v[2 * k], s4v[2 * k + 1]);
        d8v[k] = f2sub(s4v[2 * k], s4v[2 * k + 1]);
    }

    ull sc2 = __ldg(&g_sc2);  // (prod cos)^2, restores deferred scale

    ull ex = f2mul(sc2, f2sub(s8v[0], s8v[1]));                               // qubit 0
    ull ey = f2mul(sc2, f2add(d8v[0], d8v[1]));                               // qubit 1
    ull ez = f2mul(sc2, f2add(f2add(d4v[0], d4v[1]), f2add(d4v[2], d4v[3]))); // qubit 2
    ull ew = f2mul(sc2, f2add(f2add(f2add(d2v[0], d2v[1]), f2add(d2v[2], d2v[3])),
                              f2add(f2add(d2v[4], d2v[5]), f2add(d2v[6], d2v[7])))); // qubit 3

    float exl, exh, eyl, eyh, ezl, ezh, ewl, ewh;
    upk2(ex, exl, exh);
    upk2(ey, eyl, eyh);
    upk2(ez, ezl, ezh);
    upk2(ew, ewl, ewh);

    out[2 * t]     = make_float4(exl, eyl, ezl, ewl);
    out[2 * t + 1] = make_float4(exh, eyh, ezh, ewh);
}

extern "C" void kernel_launch(void* const* d_in, const int* in_sizes, int n_in,
                              void* d_out, int out_size) {
    const float* x = (const float*)d_in[0];
    const float* w = (const float*)d_in[1];
    int nx = in_sizes[0];
    // Robustness to metadata ordering: weights vector has 12 elements.
    if (n_in >= 2 && in_sizes[0] == 12) {
        x = (const float*)d_in[1];
        w = (const float*)d_in[0];
        nx = in_sizes[1];
    }
    int B  = nx / 4;
    int B2 = B / 2;  // two batch elements per thread (B = 2^20)

    prep_kernel<<<1, 32>>>(w);
    qlayer_kernel<<<(B2 + 127) / 128, 128>>>((const float4*)x, (float4*)d_out, B2);
}

// round 9
// speedup vs baseline: 1.2607x; 1.2607x over previous
#include <cuda_runtime.h>

typedef unsigned long long ull;

#define DIM 16

// ---------- packed f32x2 helpers ----------
__device__ __forceinline__ ull pk2(float lo, float hi) {
    ull r; asm("mov.b64 %0, {%1, %2};" : "=l"(r) : "f"(lo), "f"(hi)); return r;
}
__device__ __forceinline__ void upk2(ull v, float& lo, float& hi) {
    asm("mov.b64 {%0, %1}, %2;" : "=f"(lo), "=f"(hi) : "l"(v));
}
__device__ __forceinline__ ull f2mul(ull a, ull b) {
    ull r; asm("mul.rn.f32x2 %0, %1, %2;" : "=l"(r) : "l"(a), "l"(b)); return r;
}
__device__ __forceinline__ ull f2add(ull a, ull b) {
    ull r; asm("add.rn.f32x2 %0, %1, %2;" : "=l"(r) : "l"(a), "l"(b)); return r;
}
__device__ __forceinline__ ull f2fma(ull a, ull b, ull c) {
    ull r; asm("fma.rn.f32x2 %0, %1, %2, %3;" : "=l"(r) : "l"(a), "l"(b), "l"(c)); return r;
}
// a - b  ==  fma((-1,-1), b, a): one fma-pipe op.
#define NEG1_PK 0xBF800000BF800000ULL
__device__ __forceinline__ ull f2sub(ull a, ull b) { return f2fma(NEG1_PK, b, a); }
// packed negate: flip both fp32 sign bits (ALU pipe - near idle here).
__device__ __forceinline__ ull f2neg(ull a) { return a ^ 0x8000000080000000ULL; }

// Ring-CNOT permutation: new_state[i] = state[PERM[i]] (free register rename).
__device__ __forceinline__ void apply_perm(ull st[DIM]) {
    const int PERM[DIM] = {0, 13, 3, 14, 6, 11, 5, 8, 12, 1, 15, 2, 10, 7, 9, 4};
    ull tmp[DIM];
#pragma unroll
    for (int i = 0; i < DIM; i++) tmp[i] = st[PERM[i]];
#pragma unroll
    for (int i = 0; i < DIM; i++) st[i] = tmp[i];
}

// Tangent-shear RY on bit (scale c deferred): u' = u - t*v ; v' = t*u + v
// T2 loaded from smem at use site (broadcast LDS, short live range).
__device__ __forceinline__ void apply_ry_shear(ull st[DIM], int bit, const ull* tp) {
    const ull T2  = *tp;
    const ull NT2 = f2neg(T2);
    const int stride = 1 << bit;
#pragma unroll
    for (int i = 0; i < DIM; i++) {
        if (i & stride) continue;
        ull u = st[i];
        ull v = st[i + stride];
        st[i]          = f2fma(NT2, v, u);
        st[i + stride] = f2fma(T2, u, v);
    }
}

#define GRID_BLOCKS 1824   // 12 CTAs/SM x 152 SMs (GB300)

__global__ void __launch_bounds__(128, 12)
qlayer_kernel(const float4* __restrict__ x, const float* __restrict__ w,
              float4* __restrict__ out, int B2) {
    // Block-level prep of batch-uniform constants (replaces the prep kernel):
    //  s_tpk[r] = packed (t, t), t = tan(w[4+r]/2)  (layers 1,2)
    //  s_sc2    = packed (S, S), S = (prod cos)^2   (deferred scale)
    //  s_h[q]   = 0.5 * w[q]                        (layer-0 fused angles)
    __shared__ __align__(16) ull   s_tpk[8];
    __shared__ ull                 s_sc2;
    __shared__ __align__(16) float s_h[4];
    __shared__ float               s_c[8];

    int k = threadIdx.x;
    if (k < 4) {
        s_h[k] = 0.5f * w[k];
    } else if (k < 12) {
        float s, c;
        sincosf(0.5f * w[k], &s, &c);   // precise trig, once per block
        s_tpk[k - 4] = pk2(s / c, s / c);
        s_c[k - 4]   = c;
    }
    __syncthreads();
    if (k == 0) {
        float prod = 1.0f;
#pragma unroll
        for (int r = 0; r < 8; r++) prod *= s_c[r];
        float sc = prod * prod;
        s_sc2 = pk2(sc, sc);
    }
    __syncthreads();

    // Grid-stride loop: one wave of CTAs, ~2-3 circuit iterations per thread.
    for (int t = blockIdx.x * blockDim.x + threadIdx.x; t < B2;
         t += GRID_BLOCKS * 128) {

        float4 xa = x[2 * t];
        float4 xb = x[2 * t + 1];
        float4 h  = *(const float4*)s_h;

        // Fused layer-0 angles: theta_q/2 = 0.5*x_q + 0.5*w_0q, fast sincos.
        float ca[4], sa[4], cb[4], sb[4];
        __sincosf(fmaf(0.5f, xa.x, h.x), &sa[0], &ca[0]);
        __sincosf(fmaf(0.5f, xa.y, h.y), &sa[1], &ca[1]);
        __sincosf(fmaf(0.5f, xa.z, h.z), &sa[2], &ca[2]);
        __sincosf(fmaf(0.5f, xa.w, h.w), &sa[3], &ca[3]);
        __sincosf(fmaf(0.5f, xb.x, h.x), &sb[0], &cb[0]);
        __sincosf(fmaf(0.5f, xb.y, h.y), &sb[1], &cb[1]);
        __sincosf(fmaf(0.5f, xb.z, h.z), &sb[2], &cb[2]);
        __sincosf(fmaf(0.5f, xb.w, h.w), &sb[3], &cb[3]);

        ull C[4], S[4];
#pragma unroll
        for (int q = 0; q < 4; q++) {
            C[q] = pk2(ca[q], cb[q]);
            S[q] = pk2(sa[q], sb[q]);
        }

        // Tensor-product initial state (bit layout: qubit q <-> bit 3-q).
        ull A[4]  = {f2mul(C[0], C[1]), f2mul(C[0], S[1]),
                     f2mul(S[0], C[1]), f2mul(S[0], S[1])};
        ull Bv[4] = {f2mul(C[2], C[3]), f2mul(C[2], S[3]),
                     f2mul(S[2], C[3]), f2mul(S[2], S[3])};

        ull st[DIM];
#pragma unroll
        for (int i = 0; i < DIM; i++) st[i] = f2mul(A[i >> 2], Bv[i & 3]);

        // Layer 0's RYs are fused above -> just its ring permutation.
        apply_perm(st);

        // Layers 1,2: 4 tangent-shear RYs + permutation each (scales deferred).
#pragma unroll
        for (int L = 0; L < 2; L++) {
#pragma unroll
            for (int q = 0; q < 4; q++) {
                apply_ry_shear(st, 3 - q, &s_tpk[L * 4 + q]);
            }
            apply_perm(st);
        }

        // Probabilities + shared sum/difference tree for the 4 Z expectations.
        ull p[DIM];
#pragma unroll
        for (int i = 0; i < DIM; i++) p[i] = f2mul(st[i], st[i]);

        ull s2v[8], d2v[8];
#pragma unroll
        for (int kk = 0; kk < 8; kk++) {
            s2v[kk] = f2add(p[2 * kk], p[2 * kk + 1]);
            d2v[kk] = f2sub(p[2 * kk], p[2 * kk + 1]);
        }
        ull s4v[4], d4v[4];
#pragma unroll
        for (int kk = 0; kk < 4; kk++) {
            s4v[kk] = f2add(s2v[2 * kk], s2v[2 * kk + 1]);
            d4v[kk] = f2sub(s2v[2 * kk], s2v[2 * kk + 1]);
        }
        ull s8v[2], d8v[2];
#pragma unroll
        for (int kk = 0; kk < 2; kk++) {
            s8v[kk] = f2add(s4v[2 * kk], s4v[2 * kk + 1]);
            d8v[kk] = f2sub(s4v[2 * kk], s4v[2 * kk + 1]);
        }

        ull sc2 = s_sc2;  // (prod cos)^2, restores deferred scale

        ull ex = f2mul(sc2, f2sub(s8v[0], s8v[1]));                               // q0
        ull ey = f2mul(sc2, f2add(d8v[0], d8v[1]));                               // q1
        ull ez = f2mul(sc2, f2add(f2add(d4v[0], d4v[1]), f2add(d4v[2], d4v[3]))); // q2
        ull ew = f2mul(sc2, f2add(f2add(f2add(d2v[0], d2v[1]), f2add(d2v[2], d2v[3])),
                                  f2add(f2add(d2v[4], d2v[5]), f2add(d2v[6], d2v[7])))); // q3

        float exl, exh, eyl, eyh, ezl, ezh, ewl, ewh;
        upk2(ex, exl, exh);
        upk2(ey, eyl, eyh);
        upk2(ez, ezl, ezh);
        upk2(ew, ewl, ewh);

        out[2 * t]     = make_float4(exl, eyl, ezl, ewl);
        out[2 * t + 1] = make_float4(exh, eyh, ezh, ewh);
    }
}

extern "C" void kernel_launch(void* const* d_in, const int* in_sizes, int n_in,
                              void* d_out, int out_size) {
    const float* x = (const float*)d_in[0];
    const float* w = (const float*)d_in[1];
    int nx = in_sizes[0];
    // Robustness to metadata ordering: weights vector has 12 elements.
    if (n_in >= 2 && in_sizes[0] == 12) {
        x = (const float*)d_in[1];
        w = (const float*)d_in[0];
        nx = in_sizes[1];
    }
    int B  = nx / 4;
    int B2 = B / 2;  // two batch elements per thread-iteration (B = 2^20)

    int grid = GRID_BLOCKS;
    int max_needed = (B2 + 127) / 128;
    if (grid > max_needed) grid = max_needed;

    qlayer_kernel<<<grid, 128>>>((const float4*)x, w, (float4*)d_out, B2);
}